// round 1
// baseline (speedup 1.0000x reference)
#include <cuda_runtime.h>
#include <cuda_bf16.h>

// Problem constants (shapes fixed by setup_inputs)
#define N_TOT 8192
#define D     128
#define IPC_C 512
#define ROW0  7680   // bz - IPC : first row that matters
#define NCOL  7680   // unmasked columns span [0, 7680)
#define ECOLS 1024   // easy region: cols [0, 1024); hard: [1024, 7680)

#define BM 64
#define BN 64
#define KT 64
#define SPAD 65      // smem row stride (pad) to avoid bank conflicts

__device__ float g_invnorm[N_TOT];
__device__ int   g_maxE[IPC_C];
__device__ int   g_maxH[IPC_C];

// Order-preserving float <-> int encoding for atomicMax on signed ints.
__device__ __forceinline__ int f2o(float f) {
    int i = __float_as_int(f);
    return i >= 0 ? i : (i ^ 0x7FFFFFFF);
}
__device__ __forceinline__ float o2f(int o) {
    return __int_as_float(o >= 0 ? o : (o ^ 0x7FFFFFFF));
}

// Kernel 1: per-row inverse norms (1 warp per row) + init of max arrays.
__global__ void __launch_bounds__(256) norm_init_kernel(const float* __restrict__ f) {
    int row  = blockIdx.x * 8 + (threadIdx.x >> 5);
    int lane = threadIdx.x & 31;
    float4 v = ((const float4*)(f + (size_t)row * D))[lane];   // 32 lanes * 4 = 128
    float s = v.x * v.x + v.y * v.y + v.z * v.z + v.w * v.w;
    #pragma unroll
    for (int o = 16; o; o >>= 1) s += __shfl_xor_sync(0xffffffffu, s, o);
    if (lane == 0) g_invnorm[row] = 1.0f / fmaxf(sqrtf(s), 1e-12f);

    int gtid = blockIdx.x * 256 + threadIdx.x;
    if (gtid < IPC_C) {
        g_maxE[gtid] = (int)0x80000000;   // -inf in ordered encoding
        g_maxH[gtid] = (int)0x80000000;
    }
}

// Kernel 2: 512x7680x128 fp32 GEMM with row-max epilogue.
// Block: 256 threads -> 64x64 output tile, thread -> 4x4.
// grid.x = 120 column tiles (tiles [0,16) are the "easy" region),
// grid.y = 8 row tiles over the last 512 rows.
__global__ void __launch_bounds__(256) maxdot_kernel(const float* __restrict__ f) {
    __shared__ float As[BM][SPAD];
    __shared__ float Bs[BN][SPAD];

    int tid = threadIdx.x;
    int tx = tid & 15;     // column group
    int ty = tid >> 4;     // row group
    int rowBase = ROW0 + blockIdx.y * BM;
    int colBase = blockIdx.x * BN;

    float acc[4][4] = {};

    for (int kt = 0; kt < D; kt += KT) {
        // Cooperative load: 64 rows x 64 floats each for A and B (float4, coalesced).
        #pragma unroll
        for (int t = 0; t < 4; t++) {
            int lin = tid + t * 256;      // float4 index, 1024 total per tile
            int r   = lin >> 4;           // 16 float4 per row
            int k4  = lin & 15;
            float4 va = __ldg((const float4*)(f + (size_t)(rowBase + r) * D + kt) + k4);
            As[r][k4 * 4 + 0] = va.x; As[r][k4 * 4 + 1] = va.y;
            As[r][k4 * 4 + 2] = va.z; As[r][k4 * 4 + 3] = va.w;
            float4 vb = __ldg((const float4*)(f + (size_t)(colBase + r) * D + kt) + k4);
            Bs[r][k4 * 4 + 0] = vb.x; Bs[r][k4 * 4 + 1] = vb.y;
            Bs[r][k4 * 4 + 2] = vb.z; Bs[r][k4 * 4 + 3] = vb.w;
        }
        __syncthreads();

        #pragma unroll 16
        for (int k = 0; k < KT; k++) {
            float a[4], b[4];
            #pragma unroll
            for (int i = 0; i < 4; i++) a[i] = As[ty * 4 + i][k];
            #pragma unroll
            for (int j = 0; j < 4; j++) b[j] = Bs[tx * 4 + j][k];
            #pragma unroll
            for (int i = 0; i < 4; i++)
                #pragma unroll
                for (int j = 0; j < 4; j++)
                    acc[i][j] = fmaf(a[i], b[j], acc[i][j]);
        }
        __syncthreads();
    }

    // Epilogue: scale to cosine similarity, row-max, reduce across tx, atomicMax.
    float invc[4];
    #pragma unroll
    for (int j = 0; j < 4; j++) invc[j] = g_invnorm[colBase + tx * 4 + j];
    const bool easy = (colBase < ECOLS);

    #pragma unroll
    for (int i = 0; i < 4; i++) {
        int grow = rowBase + ty * 4 + i;
        float invr = g_invnorm[grow];
        float m = -2.0f;
        #pragma unroll
        for (int j = 0; j < 4; j++)
            m = fmaxf(m, acc[i][j] * invr * invc[j]);
        // reduce across the 16 tx lanes (lane bits 0..3 are tx)
        #pragma unroll
        for (int o = 8; o; o >>= 1)
            m = fmaxf(m, __shfl_xor_sync(0xffffffffu, m, o));
        if (tx == 0) {
            int* dst = easy ? g_maxE : g_maxH;
            atomicMax(&dst[grow - ROW0], f2o(m));
        }
    }
}

// Kernel 3: loss = mean_i log(1 + exp((VCH - VCE)/0.1)) * a
__global__ void __launch_bounds__(512) finalize_kernel(const float* __restrict__ a,
                                                       float* __restrict__ out) {
    __shared__ float red[512];
    int t = threadIdx.x;
    float e = o2f(g_maxE[t]);
    float h = o2f(g_maxH[t]);
    float loss = log1pf(expf((h - e) * 10.0f));   // 1/SIGMA1 = 10
    red[t] = loss;
    __syncthreads();
    #pragma unroll
    for (int s = 256; s; s >>= 1) {
        if (t < s) red[t] += red[t + s];
        __syncthreads();
    }
    if (t == 0) out[0] = a[0] * red[0] * (1.0f / 512.0f);
}

extern "C" void kernel_launch(void* const* d_in, const int* in_sizes, int n_in,
                              void* d_out, int out_size) {
    const float* fvec = (const float*)d_in[0];   // [8192,128] f32
    // d_in[1] = Lvec (unused by the reference math)
    const float* a    = (const float*)d_in[2];   // scalar f32
    float* out = (float*)d_out;

    norm_init_kernel<<<N_TOT / 8, 256>>>(fvec);
    maxdot_kernel<<<dim3(NCOL / BN, IPC_C / BM), 256>>>(fvec);
    finalize_kernel<<<1, 512>>>(a, out);
}

// round 2
// speedup vs baseline: 1.0709x; 1.0709x over previous
#include <cuda_runtime.h>
#include <cuda_bf16.h>
#include <mma.h>

using namespace nvcuda;

// Problem constants (shapes fixed by setup_inputs)
#define N_TOT 8192
#define D     128
#define IPC_C 512
#define ROW0  7680   // bz - IPC : first interesting row
#define NCOL  7680   // unmasked columns span [0, 7680)
#define BM    64
#define BN    128
#define NT    (NCOL / BN)      // 60 column tiles
#define ET    (1024 / BN)      // tiles [0,8) are the "easy" region
#define LDS_A 132              // padded smem stride (multiple of 4 for wmma)

// Partial per-(row, column-tile) maxima; fully rewritten each replay.
__device__ float g_part[IPC_C * NT];

// Dynamic smem layout (floats):
//   As   [64 ][132]   (reused as C[64][132] for the epilogue)
//   Bs   [128][132]
//   invA [64], invB[128]
#define SM_AS   0
#define SM_BS   (64 * LDS_A)
#define SM_INVA (SM_BS + 128 * LDS_A)
#define SM_INVB (SM_INVA + 64)
#define SM_FLOATS (SM_INVB + 128)

__global__ void __launch_bounds__(256) maxdot_tc_kernel(const float* __restrict__ f) {
    extern __shared__ float sm[];
    float* As = sm + SM_AS;
    float* Bs = sm + SM_BS;
    float* invA = sm + SM_INVA;
    float* invB = sm + SM_INVB;

    const int tid  = threadIdx.x;
    const int lane = tid & 31;
    const int w    = tid >> 5;          // warp 0..7
    const int wm   = w >> 2;            // 0..1  (M position)
    const int wn   = w & 3;             // 0..3  (N position)
    const int rowBase = ROW0 + blockIdx.y * BM;
    const int colBase = blockIdx.x * BN;

    // ---- stage A (64x128) and B (128x128) into smem, float4 coalesced ----
    #pragma unroll
    for (int t = 0; t < 8; t++) {
        int idx = tid + t * 256;        // float4 index, 2048 total for A
        int r = idx >> 5, c4 = idx & 31;
        float4 v = __ldg((const float4*)(f + (size_t)(rowBase + r) * D) + c4);
        *(float4*)(As + r * LDS_A + c4 * 4) = v;
    }
    #pragma unroll
    for (int t = 0; t < 16; t++) {
        int idx = tid + t * 256;        // 4096 float4 for B
        int r = idx >> 5, c4 = idx & 31;
        float4 v = __ldg((const float4*)(f + (size_t)(colBase + r) * D) + c4);
        *(float4*)(Bs + r * LDS_A + c4 * 4) = v;
    }
    __syncthreads();

    // ---- per-row inverse norms from smem (192 rows, 24 per warp) ----
    #pragma unroll
    for (int s = 0; s < 24; s++) {
        int rr = w * 24 + s;
        const float* p = (rr < 64) ? (As + rr * LDS_A) : (Bs + (rr - 64) * LDS_A);
        float acc = 0.f;
        #pragma unroll
        for (int q = 0; q < 4; q++) { float x = p[lane + 32 * q]; acc = fmaf(x, x, acc); }
        #pragma unroll
        for (int o = 16; o; o >>= 1) acc += __shfl_xor_sync(0xffffffffu, acc, o);
        if (lane == 0) {
            float inv = 1.0f / fmaxf(sqrtf(acc), 1e-12f);
            if (rr < 64) invA[rr] = inv; else invB[rr - 64] = inv;
        }
    }
    __syncthreads();

    // ---- fold invnorm + convert to tf32 (RNA) in place ----
    #pragma unroll
    for (int t = 0; t < 32; t++) {
        int i = tid + t * 256;          // 8192 A elements
        int r = i >> 7, c = i & 127;
        As[r * LDS_A + c] = wmma::__float_to_tf32(As[r * LDS_A + c] * invA[r]);
    }
    #pragma unroll
    for (int t = 0; t < 64; t++) {
        int i = tid + t * 256;          // 16384 B elements
        int r = i >> 7, c = i & 127;
        Bs[r * LDS_A + c] = wmma::__float_to_tf32(Bs[r * LDS_A + c] * invB[r]);
    }
    __syncthreads();

    // ---- tensor-core GEMM: warp computes 32x32 via 2x2 fragments ----
    wmma::fragment<wmma::accumulator, 16, 16, 8, float> cf[2][2];
    #pragma unroll
    for (int i = 0; i < 2; i++)
        #pragma unroll
        for (int j = 0; j < 2; j++) wmma::fill_fragment(cf[i][j], 0.0f);

    #pragma unroll
    for (int k8 = 0; k8 < D / 8; k8++) {
        wmma::fragment<wmma::matrix_a, 16, 16, 8, wmma::precision::tf32, wmma::row_major> af[2];
        wmma::fragment<wmma::matrix_b, 16, 16, 8, wmma::precision::tf32, wmma::col_major> bf[2];
        #pragma unroll
        for (int i = 0; i < 2; i++)
            wmma::load_matrix_sync(af[i], As + (wm * 32 + i * 16) * LDS_A + k8 * 8, LDS_A);
        #pragma unroll
        for (int j = 0; j < 2; j++)
            wmma::load_matrix_sync(bf[j], Bs + (wn * 32 + j * 16) * LDS_A + k8 * 8, LDS_A);
        #pragma unroll
        for (int i = 0; i < 2; i++)
            #pragma unroll
            for (int j = 0; j < 2; j++)
                wmma::mma_sync(cf[i][j], af[i], bf[j], cf[i][j]);
    }
    __syncthreads();   // everyone done reading As/Bs

    // ---- spill accumulators (already cosine sims) into the As region ----
    float* C = As;     // 64 x 132
    #pragma unroll
    for (int i = 0; i < 2; i++)
        #pragma unroll
        for (int j = 0; j < 2; j++)
            wmma::store_matrix_sync(C + (wm * 32 + i * 16) * LDS_A + (wn * 32 + j * 16),
                                    cf[i][j], LDS_A, wmma::mem_row_major);
    __syncthreads();

    // ---- row max over the 128 tile columns -> g_part ----
    #pragma unroll
    for (int s = 0; s < 8; s++) {
        int r = w * 8 + s;
        const float* p = C + r * LDS_A;
        float m = fmaxf(fmaxf(p[lane], p[lane + 32]), fmaxf(p[lane + 64], p[lane + 96]));
        #pragma unroll
        for (int o = 16; o; o >>= 1) m = fmaxf(m, __shfl_xor_sync(0xffffffffu, m, o));
        if (lane == 0)
            g_part[(blockIdx.y * BM + r) * NT + blockIdx.x] = m;
    }
}

// loss = a * mean_i log(1 + exp((VCH_i - VCE_i) / 0.1))
__global__ void __launch_bounds__(512) finalize_kernel(const float* __restrict__ a,
                                                       float* __restrict__ out) {
    __shared__ float red[512];
    int t = threadIdx.x;
    const float* p = g_part + t * NT;
    float e = -2.f, h = -2.f;
    #pragma unroll
    for (int j = 0; j < ET; j++)  e = fmaxf(e, p[j]);
    #pragma unroll
    for (int j = ET; j < NT; j++) h = fmaxf(h, p[j]);
    red[t] = log1pf(expf((h - e) * 10.0f));   // 1/SIGMA1 = 10
    __syncthreads();
    #pragma unroll
    for (int s = 256; s; s >>= 1) {
        if (t < s) red[t] += red[t + s];
        __syncthreads();
    }
    if (t == 0) out[0] = a[0] * red[0] * (1.0f / 512.0f);
}

extern "C" void kernel_launch(void* const* d_in, const int* in_sizes, int n_in,
                              void* d_out, int out_size) {
    const float* fvec = (const float*)d_in[0];   // [8192,128] f32
    // d_in[1] = Lvec (dead in the reference math)
    const float* a    = (const float*)d_in[2];   // scalar f32
    float* out = (float*)d_out;

    static_assert(SM_FLOATS * 4 <= 110 * 1024, "smem budget");
    cudaFuncSetAttribute(maxdot_tc_kernel,
                         cudaFuncAttributeMaxDynamicSharedMemorySize, SM_FLOATS * 4);

    maxdot_tc_kernel<<<dim3(NT, IPC_C / BM), 256, SM_FLOATS * 4>>>(fvec);
    finalize_kernel<<<1, 512>>>(a, out);
}

// round 4
// speedup vs baseline: 3.1458x; 2.9375x over previous
#include <cuda_runtime.h>
#include <cuda_bf16.h>
#include <cstdint>

// ---------------- problem constants ----------------
#define N_TOT 8192
#define D     128
#define IPC_C 512
#define ROW0  7680            // bz - IPC
#define NCOL  7680            // unmasked columns [0, 7680)
#define BM    128
#define BN    256
#define NTIL  (NCOL / BN)     // 30 column tiles
#define ETIL  (1024 / BN)     // tiles [0,4) are the easy region (exact boundary)
#define NBLK  (NTIL * (IPC_C / BM))   // 120 blocks
#define LDA   132             // padded smem stride (floats)

// ---------------- device globals (no allocs allowed) ----------------
__device__ float g_fn[N_TOT * D];              // normalized, tf32-rounded
__device__ float g_part[NTIL * IPC_C];         // [colTile][row] partial maxima
__device__ int   g_done;                       // zero-init; returns to 0 each replay

// ---------------- kernel 1: normalize + tf32 round ----------------
__global__ void __launch_bounds__(256) prep_kernel(const float* __restrict__ f) {
    int row  = blockIdx.x * 8 + (threadIdx.x >> 5);
    int lane = threadIdx.x & 31;
    float4 v = ((const float4*)(f + (size_t)row * D))[lane];
    float s = v.x * v.x + v.y * v.y + v.z * v.z + v.w * v.w;
    #pragma unroll
    for (int o = 16; o; o >>= 1) s += __shfl_xor_sync(0xffffffffu, s, o);
    float inv = rsqrtf(s);
    // guard (norm >= 1e-12): rsqrtf fine for random normal rows; clamp anyway
    if (!(s > 1e-24f)) inv = 1e12f;

    float x[4] = {v.x * inv, v.y * inv, v.z * inv, v.w * inv};
    uint32_t t[4];
    #pragma unroll
    for (int j = 0; j < 4; j++)
        asm("cvt.rna.tf32.f32 %0, %1;" : "=r"(t[j]) : "f"(x[j]));
    *(uint4*)(g_fn + (size_t)row * D + lane * 4) = *(uint4*)t;
}

// ---------------- kernel 2: tf32 mma GEMM + row-max + fused finalize ----------------
// 512 threads = 16 warps in a 4(m) x 4(n) grid; each warp: 32x64 output.
// smem: As[128][132] floats, Bs[256][132] floats (198 KB).
#define SMEM_FLOATS (BM * LDA + BN * LDA)

__global__ void __launch_bounds__(512) gemm_kernel(const float* __restrict__ a_scl,
                                                   float* __restrict__ out) {
    extern __shared__ float sm[];
    float* As = sm;                 // [128][132]
    float* Bs = sm + BM * LDA;      // [256][132]

    const int tid  = threadIdx.x;
    const int lane = tid & 31;
    const int w    = tid >> 5;
    const int wm   = w >> 2;        // 0..3 -> 32-row strip
    const int wn   = w & 3;         // 0..3 -> 64-col strip
    const int q    = lane >> 2;     // group id (0..7)
    const int tig  = lane & 3;      // thread-in-group
    const int rowBase = ROW0 + blockIdx.y * BM;
    const int colBase = blockIdx.x * BN;

    // ---- stage A (128x128) and B (256x128), float4 coalesced ----
    #pragma unroll
    for (int t = 0; t < 8; t++) {
        int idx = tid + t * 512;            // 4096 float4
        int r = idx >> 5, c4 = idx & 31;
        float4 v = __ldg((const float4*)(g_fn + (size_t)(rowBase + r) * D) + c4);
        *(float4*)(As + r * LDA + c4 * 4) = v;
    }
    #pragma unroll
    for (int t = 0; t < 16; t++) {
        int idx = tid + t * 512;            // 8192 float4
        int r = idx >> 5, c4 = idx & 31;
        float4 v = __ldg((const float4*)(g_fn + (size_t)(colBase + r) * D) + c4);
        *(float4*)(Bs + r * LDA + c4 * 4) = v;
    }
    __syncthreads();

    // ---- mainloop: 16 K-steps of m16n8k8 tf32 ----
    float acc[2][8][4];
    #pragma unroll
    for (int mt = 0; mt < 2; mt++)
        #pragma unroll
        for (int nt = 0; nt < 8; nt++)
            #pragma unroll
            for (int e = 0; e < 4; e++) acc[mt][nt][e] = 0.f;

    const uint32_t* Au = (const uint32_t*)As;
    const uint32_t* Bu = (const uint32_t*)Bs;

    #pragma unroll
    for (int s = 0; s < 16; s++) {
        const int k0 = s * 8 + tig;
        uint32_t af[2][4];
        #pragma unroll
        for (int mt = 0; mt < 2; mt++) {
            int r0 = wm * 32 + mt * 16 + q;
            af[mt][0] = Au[r0 * LDA + k0];
            af[mt][1] = Au[(r0 + 8) * LDA + k0];
            af[mt][2] = Au[r0 * LDA + k0 + 4];
            af[mt][3] = Au[(r0 + 8) * LDA + k0 + 4];
        }
        uint32_t bf[8][2];
        #pragma unroll
        for (int nt = 0; nt < 8; nt++) {
            int n0 = wn * 64 + nt * 8 + q;
            bf[nt][0] = Bu[n0 * LDA + k0];
            bf[nt][1] = Bu[n0 * LDA + k0 + 4];
        }
        #pragma unroll
        for (int mt = 0; mt < 2; mt++)
            #pragma unroll
            for (int nt = 0; nt < 8; nt++)
                asm volatile(
                    "mma.sync.aligned.m16n8k8.row.col.f32.tf32.tf32.f32 "
                    "{%0,%1,%2,%3}, {%4,%5,%6,%7}, {%8,%9}, {%0,%1,%2,%3};"
                    : "+f"(acc[mt][nt][0]), "+f"(acc[mt][nt][1]),
                      "+f"(acc[mt][nt][2]), "+f"(acc[mt][nt][3])
                    : "r"(af[mt][0]), "r"(af[mt][1]), "r"(af[mt][2]), "r"(af[mt][3]),
                      "r"(bf[nt][0]), "r"(bf[nt][1]));
    }
    __syncthreads();   // everyone done reading smem before pmax overwrites it

    // ---- row max: per-thread -> per-group shfl -> cross-warp via smem ----
    float* pm = As;    // [4(wn)][128] row maxima
    #pragma unroll
    for (int mt = 0; mt < 2; mt++) {
        float mlo = -2.f, mhi = -2.f;
        #pragma unroll
        for (int nt = 0; nt < 8; nt++) {
            mlo = fmaxf(mlo, fmaxf(acc[mt][nt][0], acc[mt][nt][1]));
            mhi = fmaxf(mhi, fmaxf(acc[mt][nt][2], acc[mt][nt][3]));
        }
        #pragma unroll
        for (int o = 1; o < 4; o <<= 1) {
            mlo = fmaxf(mlo, __shfl_xor_sync(0xffffffffu, mlo, o));
            mhi = fmaxf(mhi, __shfl_xor_sync(0xffffffffu, mhi, o));
        }
        if (tig == 0) {
            int r = wm * 32 + mt * 16 + q;
            pm[wn * 128 + r]     = mlo;
            pm[wn * 128 + r + 8] = mhi;
        }
    }
    __syncthreads();

    if (tid < BM) {
        float m = fmaxf(fmaxf(pm[tid], pm[128 + tid]),
                        fmaxf(pm[256 + tid], pm[384 + tid]));
        g_part[blockIdx.x * IPC_C + blockIdx.y * BM + tid] = m;
    }
    __syncthreads();

    // ---- last-block-done fused finalize ----
    __shared__ int isLast;
    __shared__ float red[512];
    if (tid == 0) {
        __threadfence();
        isLast = (atomicAdd(&g_done, 1) == NBLK - 1);
    }
    __syncthreads();
    if (!isLast) return;
    if (tid == 0) __threadfence();
    __syncthreads();

    float e = -2.f, h = -2.f;
    #pragma unroll
    for (int j = 0; j < ETIL; j++)     e = fmaxf(e, g_part[j * IPC_C + tid]);
    #pragma unroll
    for (int j = ETIL; j < NTIL; j++)  h = fmaxf(h, g_part[j * IPC_C + tid]);
    red[tid] = log1pf(expf((h - e) * 10.0f));   // 1/SIGMA1 = 10
    __syncthreads();
    #pragma unroll
    for (int s2 = 256; s2; s2 >>= 1) {
        if (tid < s2) red[tid] += red[tid + s2];
        __syncthreads();
    }
    if (tid == 0) {
        out[0] = a_scl[0] * red[0] * (1.0f / 512.0f);
        g_done = 0;      // reset for the next graph replay
    }
}

extern "C" void kernel_launch(void* const* d_in, const int* in_sizes, int n_in,
                              void* d_out, int out_size) {
    const float* fvec = (const float*)d_in[0];   // [8192,128] f32
    // d_in[1] = Lvec (dead in the reference math)
    const float* a    = (const float*)d_in[2];   // scalar f32
    float* out = (float*)d_out;

    cudaFuncSetAttribute(gemm_kernel,
                         cudaFuncAttributeMaxDynamicSharedMemorySize,
                         SMEM_FLOATS * 4);

    prep_kernel<<<N_TOT / 8, 256>>>(fvec);
    gemm_kernel<<<dim3(NTIL, IPC_C / BM), 512, SMEM_FLOATS * 4>>>(a, out);
}